// round 16
// baseline (speedup 1.0000x reference)
#include <cuda_runtime.h>

#define G  7
#define GG 49            // G*G
#define CH 1470          // 30*GG

__device__ float        g_accum = 0.0f;
__device__ unsigned int g_count = 0;

__device__ __forceinline__ float warp_sum(float v) {
    #pragma unroll
    for (int o = 16; o > 0; o >>= 1) v += __shfl_down_sync(0xffffffffu, v, o);
    return v;
}

__global__ __launch_bounds__(256) void yolo_loss_kernel(
    const float* __restrict__ pred,
    const float* __restrict__ lab,
    float* __restrict__ out,
    int total, float invB)
{
    int idx = blockIdx.x * 256 + threadIdx.x;

    float loss = 0.0f;
    if (idx < total) {
        const int b    = idx / GG;
        const int cell = idx - b * GG;
        const int m    = cell / G;     // dim-2 index, pairs with x
        const int n    = cell % G;     // dim-3 index, pairs with y

        const float* p = pred + (long long)b * CH + cell;
        const float* l = lab  + (long long)b * CH + cell;

        // --- always-needed loads (3 independent, in flight together) ---
        float l4 = l[4 * GG];
        float p4 = p[4 * GG];
        float p9 = p[9 * GG];

        const bool obj = (l4 == 1.0f);

        if (obj) {
            // pred channels 0..9 (4 and 9 already loaded)
            float pv[10];
            pv[4] = p4; pv[9] = p9;
            pv[0] = p[0 * GG]; pv[1] = p[1 * GG]; pv[2] = p[2 * GG]; pv[3] = p[3 * GG];
            pv[5] = p[5 * GG]; pv[6] = p[6 * GG]; pv[7] = p[7 * GG]; pv[8] = p[8 * GG];

            // label channels 0..8 (4 already loaded; 9 unused)
            float lv[9];
            lv[4] = l4;
            lv[0] = l[0 * GG]; lv[1] = l[1 * GG]; lv[2] = l[2 * GG]; lv[3] = l[3 * GG];
            lv[5] = l[5 * GG]; lv[6] = l[6 * GG]; lv[7] = l[7 * GG]; lv[8] = l[8 * GG];

            const float mf = (float)m;
            const float nf = (float)n;
            const float invG = 1.0f / (float)G;

            // --- boxes in xyxy ---
            float cx1 = (pv[0] + mf) * invG, cy1 = (pv[1] + nf) * invG;
            float x1a = cx1 - pv[2] * 0.5f, y1a = cy1 - pv[3] * 0.5f;
            float x2a = cx1 + pv[2] * 0.5f, y2a = cy1 + pv[3] * 0.5f;
            float cx2 = (pv[5] + mf) * invG, cy2 = (pv[6] + nf) * invG;
            float x1b = cx2 - pv[7] * 0.5f, y1b = cy2 - pv[8] * 0.5f;
            float x2b = cx2 + pv[7] * 0.5f, y2b = cy2 + pv[8] * 0.5f;
            float cxg = (lv[0] + mf) * invG, cyg = (lv[1] + nf) * invG;
            float x1g = cxg - lv[2] * 0.5f, y1g = cyg - lv[3] * 0.5f;
            float x2g = cxg + lv[2] * 0.5f, y2g = cyg + lv[3] * 0.5f;

            // --- iou(box1, boxg) ---
            float iw1 = fmaxf(fminf(x2a, x2g) - fmaxf(x1a, x1g), 0.0f);
            float ih1 = fmaxf(fminf(y2a, y2g) - fmaxf(y1a, y1g), 0.0f);
            float inter1 = iw1 * ih1;
            float area_a = (x2a - x1a) * (y2a - y1a);
            float area_g = (x2g - x1g) * (y2g - y1g);
            float iou1 = (inter1 > 0.0f) ? inter1 / (area_a + area_g - inter1) : 0.0f;

            // --- iou(box2, boxg) ---
            float iw2 = fmaxf(fminf(x2b, x2g) - fmaxf(x1b, x1g), 0.0f);
            float ih2 = fmaxf(fminf(y2b, y2g) - fmaxf(y1b, y1g), 0.0f);
            float inter2 = iw2 * ih2;
            float area_b = (x2b - x1b) * (y2b - y1b);
            float iou2 = (inter2 > 0.0f) ? inter2 / (area_b + area_g - inter2) : 0.0f;

            bool resp1 = (iou1 >= iou2);

            // --- coord losses ---
            float d0 = pv[0] - lv[0], d1 = pv[1] - lv[1];
            float s2 = sqrtf(pv[2]) - sqrtf(lv[2]);
            float s3 = sqrtf(pv[3]) - sqrtf(lv[3]);
            float coor1 = 5.0f * (d0 * d0 + d1 * d1 + s2 * s2 + s3 * s3);

            float d5 = pv[5] - lv[5], d6 = pv[6] - lv[6];
            float s7 = sqrtf(pv[7]) - sqrtf(lv[7]);
            float s8 = sqrtf(pv[8]) - sqrtf(lv[8]);
            float coor2 = 5.0f * (d5 * d5 + d6 * d6 + s7 * s7 + s8 * s8);

            float e1 = pv[4] - iou1;
            float e2 = pv[9] - iou2;
            float loss_b1 = coor1 + e1 * e1 + 0.5f * e2 * e2;
            float loss_b2 = coor2 + e2 * e2 + 0.5f * e1 * e1;

            // --- class loss (channels 10..29) ---
            float cls = 0.0f;
            #pragma unroll
            for (int c = 10; c < 30; c++) {
                float d = p[c * GG] - l[c * GG];
                cls = fmaf(d, d, cls);
            }

            loss = (resp1 ? loss_b1 : loss_b2) + cls;
        } else {
            loss = 0.5f * (p4 * p4 + p9 * p9);
        }
    }

    // --- block reduction ---
    __shared__ float warp_sums[8];
    float v = warp_sum(loss);
    int lane = threadIdx.x & 31;
    int wid  = threadIdx.x >> 5;
    if (lane == 0) warp_sums[wid] = v;
    __syncthreads();
    if (wid == 0) {
        float bv = (lane < 8) ? warp_sums[lane] : 0.0f;
        bv = warp_sum(bv);
        if (lane == 0) {
            atomicAdd(&g_accum, bv);
            __threadfence();
            unsigned int old = atomicInc(&g_count, gridDim.x - 1);
            if (old == gridDim.x - 1) {
                float tot = atomicExch(&g_accum, 0.0f);
                out[0] = tot * invB;
            }
        }
    }
}

extern "C" void kernel_launch(void* const* d_in, const int* in_sizes, int n_in,
                              void* d_out, int out_size) {
    const float* pred = (const float*)d_in[0];
    const float* lab  = (const float*)d_in[1];
    float* out = (float*)d_out;

    int B = in_sizes[0] / CH;        // 32768
    int total = B * GG;              // 1605632
    int threads = 256;
    int blocks = (total + threads - 1) / threads;

    yolo_loss_kernel<<<blocks, threads>>>(pred, lab, out, total, 1.0f / (float)B);
}

// round 17
// speedup vs baseline: 1.0047x; 1.0047x over previous
#include <cuda_runtime.h>

#define G  7
#define GG 49            // G*G
#define CH 1470          // 30*GG
#define THREADS 128

__device__ float        g_accum = 0.0f;
__device__ unsigned int g_count = 0;

__device__ __forceinline__ float warp_sum(float v) {
    #pragma unroll
    for (int o = 16; o > 0; o >>= 1) v += __shfl_down_sync(0xffffffffu, v, o);
    return v;
}

__global__ __launch_bounds__(THREADS) void yolo_loss_kernel(
    const float* __restrict__ pred,
    const float* __restrict__ lab,
    float* __restrict__ out,
    int total, float invB)
{
    int idx = blockIdx.x * THREADS + threadIdx.x;

    float loss = 0.0f;
    if (idx < total) {
        const int b    = idx / GG;
        const int cell = idx - b * GG;
        const int m    = cell / G;     // dim-2 index, pairs with x
        const int n    = cell % G;     // dim-3 index, pairs with y

        const float* p = pred + (long long)b * CH + cell;
        const float* l = lab  + (long long)b * CH + cell;

        // --- always-needed loads (3 independent, in flight together) ---
        float l4 = l[4 * GG];
        float p4 = p[4 * GG];
        float p9 = p[9 * GG];

        const bool obj = (l4 == 1.0f);

        if (obj) {
            // pred channels 0..9 (4 and 9 already loaded)
            float pv[10];
            pv[4] = p4; pv[9] = p9;
            pv[0] = p[0 * GG]; pv[1] = p[1 * GG]; pv[2] = p[2 * GG]; pv[3] = p[3 * GG];
            pv[5] = p[5 * GG]; pv[6] = p[6 * GG]; pv[7] = p[7 * GG]; pv[8] = p[8 * GG];

            // label channels 0..8 (4 already loaded; 9 unused)
            float lv[9];
            lv[4] = l4;
            lv[0] = l[0 * GG]; lv[1] = l[1 * GG]; lv[2] = l[2 * GG]; lv[3] = l[3 * GG];
            lv[5] = l[5 * GG]; lv[6] = l[6 * GG]; lv[7] = l[7 * GG]; lv[8] = l[8 * GG];

            const float mf = (float)m;
            const float nf = (float)n;
            const float invG = 1.0f / (float)G;

            // --- boxes in xyxy ---
            float cx1 = (pv[0] + mf) * invG, cy1 = (pv[1] + nf) * invG;
            float x1a = cx1 - pv[2] * 0.5f, y1a = cy1 - pv[3] * 0.5f;
            float x2a = cx1 + pv[2] * 0.5f, y2a = cy1 + pv[3] * 0.5f;
            float cx2 = (pv[5] + mf) * invG, cy2 = (pv[6] + nf) * invG;
            float x1b = cx2 - pv[7] * 0.5f, y1b = cy2 - pv[8] * 0.5f;
            float x2b = cx2 + pv[7] * 0.5f, y2b = cy2 + pv[8] * 0.5f;
            float cxg = (lv[0] + mf) * invG, cyg = (lv[1] + nf) * invG;
            float x1g = cxg - lv[2] * 0.5f, y1g = cyg - lv[3] * 0.5f;
            float x2g = cxg + lv[2] * 0.5f, y2g = cyg + lv[3] * 0.5f;

            // --- iou(box1, boxg) ---
            float iw1 = fmaxf(fminf(x2a, x2g) - fmaxf(x1a, x1g), 0.0f);
            float ih1 = fmaxf(fminf(y2a, y2g) - fmaxf(y1a, y1g), 0.0f);
            float inter1 = iw1 * ih1;
            float area_a = (x2a - x1a) * (y2a - y1a);
            float area_g = (x2g - x1g) * (y2g - y1g);
            float iou1 = (inter1 > 0.0f) ? inter1 / (area_a + area_g - inter1) : 0.0f;

            // --- iou(box2, boxg) ---
            float iw2 = fmaxf(fminf(x2b, x2g) - fmaxf(x1b, x1g), 0.0f);
            float ih2 = fmaxf(fminf(y2b, y2g) - fmaxf(y1b, y1g), 0.0f);
            float inter2 = iw2 * ih2;
            float area_b = (x2b - x1b) * (y2b - y1b);
            float iou2 = (inter2 > 0.0f) ? inter2 / (area_b + area_g - inter2) : 0.0f;

            bool resp1 = (iou1 >= iou2);

            // --- coord losses ---
            float d0 = pv[0] - lv[0], d1 = pv[1] - lv[1];
            float s2 = sqrtf(pv[2]) - sqrtf(lv[2]);
            float s3 = sqrtf(pv[3]) - sqrtf(lv[3]);
            float coor1 = 5.0f * (d0 * d0 + d1 * d1 + s2 * s2 + s3 * s3);

            float d5 = pv[5] - lv[5], d6 = pv[6] - lv[6];
            float s7 = sqrtf(pv[7]) - sqrtf(lv[7]);
            float s8 = sqrtf(pv[8]) - sqrtf(lv[8]);
            float coor2 = 5.0f * (d5 * d5 + d6 * d6 + s7 * s7 + s8 * s8);

            float e1 = pv[4] - iou1;
            float e2 = pv[9] - iou2;
            float loss_b1 = coor1 + e1 * e1 + 0.5f * e2 * e2;
            float loss_b2 = coor2 + e2 * e2 + 0.5f * e1 * e1;

            // --- class loss (channels 10..29) ---
            float cls = 0.0f;
            #pragma unroll
            for (int c = 10; c < 30; c++) {
                float d = p[c * GG] - l[c * GG];
                cls = fmaf(d, d, cls);
            }

            loss = (resp1 ? loss_b1 : loss_b2) + cls;
        } else {
            loss = 0.5f * (p4 * p4 + p9 * p9);
        }
    }

    // --- block reduction (128 threads = 4 warps) ---
    __shared__ float warp_sums[4];
    float v = warp_sum(loss);
    int lane = threadIdx.x & 31;
    int wid  = threadIdx.x >> 5;
    if (lane == 0) warp_sums[wid] = v;
    __syncthreads();
    if (wid == 0) {
        float bv = (lane < 4) ? warp_sums[lane] : 0.0f;
        bv = warp_sum(bv);
        if (lane == 0) {
            atomicAdd(&g_accum, bv);
            __threadfence();
            unsigned int old = atomicInc(&g_count, gridDim.x - 1);
            if (old == gridDim.x - 1) {
                float tot = atomicExch(&g_accum, 0.0f);
                out[0] = tot * invB;
            }
        }
    }
}

extern "C" void kernel_launch(void* const* d_in, const int* in_sizes, int n_in,
                              void* d_out, int out_size) {
    const float* pred = (const float*)d_in[0];
    const float* lab  = (const float*)d_in[1];
    float* out = (float*)d_out;

    int B = in_sizes[0] / CH;        // 32768
    int total = B * GG;              // 1605632
    int blocks = (total + THREADS - 1) / THREADS;

    yolo_loss_kernel<<<blocks, THREADS>>>(pred, lab, out, total, 1.0f / (float)B);
}